// round 1
// baseline (speedup 1.0000x reference)
#include <cuda_runtime.h>
#include <math.h>

#define BTOT 32768
#define KCOMP 64
#define DDIM 64
#define LOG_2PI 1.8378770664093453f

// ---- persistent scratch (no allocations allowed) ----
__device__ float  g_LinvT[KCOMP][DDIM][DDIM];  // [k][j][i] = Linv_k[i][j]
__device__ float  g_c[KCOMP][DDIM];            // c_k[i] = (Linv_k mu_k)[i]
__device__ float  g_constk[KCOMP];             // logw_k - half_log_det_k - 0.5*D*log(2pi)
__device__ float  g_logw[KCOMP];
__device__ double g_partial[512];

// ============================================================
// Kernel 0: log-softmax of weights (K=64), 1 block x 64 threads
// ============================================================
__global__ void logw_kernel(const float* __restrict__ w) {
    __shared__ float red[KCOMP];
    int t = threadIdx.x;
    float v = w[t] * 0.125f;   // gain / sqrt(K) = 1/8
    red[t] = v;
    __syncthreads();
    for (int s = 32; s > 0; s >>= 1) {
        if (t < s) red[t] = fmaxf(red[t], red[t + s]);
        __syncthreads();
    }
    float m = red[0];
    __syncthreads();
    red[t] = expf(v - m);
    __syncthreads();
    for (int s = 32; s > 0; s >>= 1) {
        if (t < s) red[t] += red[t + s];
        __syncthreads();
    }
    float lse = m + logf(red[0]);
    g_logw[t] = v - lse;
}

// ============================================================
// Kernel 1: per-component preprocess. 64 blocks x 64 threads.
// Builds L, inverts (forward substitution per column), stores
// LinvT, c, and the per-component additive constant.
// ============================================================
__global__ void prep_kernel(const float* __restrict__ means_raw,
                            const float* __restrict__ scale_raw) {
    const int k = blockIdx.x;
    const int t = threadIdx.x;
    __shared__ float L[DDIM][DDIM + 1];
    __shared__ float Y[DDIM][DDIM + 1];   // Y[j][i]: column j of Linv
    __shared__ float red[DDIM];
    __shared__ float mv[DDIM];
    const float g2 = 1.0f / 512.0f;   // 1/sqrt(K*D*D)
    const float g1 = 1.0f / 64.0f;    // 1/sqrt(K*D)

    for (int i = 0; i < DDIM; i++)
        L[i][t] = scale_raw[(k * DDIM + i) * DDIM + t] * g2;
    mv[t] = means_raw[k * DDIM + t] * g1;
    __syncthreads();

    // half_log_det = sum of pre-diagonal (since log(exp(d)) = d)
    red[t] = L[t][t];
    __syncthreads();
    for (int s = 32; s > 0; s >>= 1) {
        if (t < s) red[t] += red[t + s];
        __syncthreads();
    }
    float hld = red[0];

    // Build L row t: keep strict lower, exp on diag, zero above.
    {
        float dg = expf(L[t][t]);
        for (int j = t; j < DDIM; j++) L[t][j] = (j == t) ? dg : 0.0f;
    }
    __syncthreads();

    // Solve L * y = e_t  (column t of Linv)
    for (int i = 0; i < t; i++) Y[t][i] = 0.0f;
    Y[t][t] = 1.0f / L[t][t];
    for (int i = t + 1; i < DDIM; i++) {
        float s = 0.0f;
        for (int m = t; m < i; m++) s += L[i][m] * Y[t][m];
        Y[t][i] = -s / L[i][i];
    }
    __syncthreads();

    // LinvT[j][i] = Linv[i][j] = Y[j][i]
    for (int i = 0; i < DDIM; i++) g_LinvT[k][t][i] = Y[t][i];

    // c[t] = sum_j Linv[t][j] * mu[j] = sum_{j<=t} Y[j][t] * mu[j]
    float c = 0.0f;
    for (int j = 0; j <= t; j++) c += Y[j][t] * mv[j];
    g_c[k][t] = c;

    if (t == 0)
        g_constk[k] = g_logw[k] - hld - 0.5f * (float)DDIM * LOG_2PI;
}

// ============================================================
// Kernel 2: main GEMM + fused maha + online logsumexp.
// 512 blocks x 256 threads. Tile: 64 batch rows x 128 cols
// (2 components per iteration). Per-thread 8x4 register tile.
// ============================================================
#define SMEM_FLOATS (4096 + 8192 + 128)        // Xs + Ls + mahaS
#define SMEM_BYTES  (SMEM_FLOATS * 4 + 64 * 8) // + dred (64 doubles)

__global__ __launch_bounds__(256) void main_kernel(const float* __restrict__ x) {
    extern __shared__ float smem[];
    float*  Xs    = smem;                 // [64 j][64 b]
    float*  Ls    = smem + 4096;          // [64 j][128 c]  c = comp*64 + i
    float*  mahaS = smem + 4096 + 8192;   // [2][64]
    double* dred  = (double*)(smem + SMEM_FLOATS);

    const int tid = threadIdx.x;
    const int b0  = blockIdx.x * 64;

    // Load X tile transposed: Xs[j][b] = x[b0+b][j]
    {
        const float4* X4 = (const float4*)x;
        int b  = tid >> 2;
        int jg = tid & 3;
#pragma unroll
        for (int q = 0; q < 4; q++) {
            float4 v = X4[(size_t)(b0 + b) * 16 + jg * 4 + q];
            int j = jg * 16 + q * 4;
            Xs[(j + 0) * 64 + b] = v.x;
            Xs[(j + 1) * 64 + b] = v.y;
            Xs[(j + 2) * 64 + b] = v.z;
            Xs[(j + 3) * 64 + b] = v.w;
        }
    }

    const int h = tid & 31;   // col group: cols h*4 .. h*4+3 (0..127)
    const int g = tid >> 5;   // row group: rows g*8 .. g*8+7  (warp id)

    float runm = -INFINITY, runs = 0.0f;

    for (int kk = 0; kk < KCOMP; kk += 2) {
        __syncthreads();   // Xs ready (iter 0) / Ls free for rewrite
        // Load LinvT for 2 components into Ls
        {
            float4* Ls4 = (float4*)Ls;
            const float4* A0 = (const float4*)&g_LinvT[kk][0][0];
            const float4* A1 = (const float4*)&g_LinvT[kk + 1][0][0];
#pragma unroll
            for (int f = tid; f < 1024; f += 256) {
                int j = f >> 4, i4 = f & 15;
                Ls4[j * 32 + i4]      = A0[f];
                Ls4[j * 32 + 16 + i4] = A1[f];
            }
        }
        __syncthreads();

        float acc[8][4];
#pragma unroll
        for (int r = 0; r < 8; r++)
#pragma unroll
            for (int cc = 0; cc < 4; cc++) acc[r][cc] = 0.0f;

        const float4* Xs4 = (const float4*)Xs;
        const float4* Ls4 = (const float4*)Ls;
#pragma unroll 8
        for (int j = 0; j < 64; j++) {
            float4 xa0 = Xs4[j * 16 + g * 2];       // rows g*8..g*8+3 (broadcast in warp)
            float4 xa1 = Xs4[j * 16 + g * 2 + 1];   // rows g*8+4..g*8+7
            float4 lb  = Ls4[j * 32 + h];           // cols h*4..h*4+3
            float xr[8] = {xa0.x, xa0.y, xa0.z, xa0.w, xa1.x, xa1.y, xa1.z, xa1.w};
#pragma unroll
            for (int r = 0; r < 8; r++) {
                acc[r][0] = fmaf(xr[r], lb.x, acc[r][0]);
                acc[r][1] = fmaf(xr[r], lb.y, acc[r][1]);
                acc[r][2] = fmaf(xr[r], lb.z, acc[r][2]);
                acc[r][3] = fmaf(xr[r], lb.w, acc[r][3]);
            }
        }

        // Epilogue: subtract c, square, row-sum, reduce across col groups.
        const int comp = h >> 4;
        const float* cp = &g_c[kk + comp][(h & 15) * 4];
        float c0 = cp[0], c1 = cp[1], c2 = cp[2], c3 = cp[3];

        float rs[8];
#pragma unroll
        for (int r = 0; r < 8; r++) {
            float z0 = acc[r][0] - c0;
            float z1 = acc[r][1] - c1;
            float z2 = acc[r][2] - c2;
            float z3 = acc[r][3] - c3;
            rs[r] = z0 * z0 + z1 * z1 + z2 * z2 + z3 * z3;
        }
        // reduce within each 16-lane half of the warp (per-component)
#pragma unroll
        for (int off = 8; off > 0; off >>= 1)
#pragma unroll
            for (int r = 0; r < 8; r++)
                rs[r] += __shfl_xor_sync(0xffffffffu, rs[r], off);

        if ((h & 15) == 0) {
#pragma unroll
            for (int r = 0; r < 8; r++)
                mahaS[comp * 64 + g * 8 + r] = rs[r];
        }
        __syncthreads();

        // Online logsumexp update (threads 0..63 own row b = tid)
        if (tid < 64) {
#pragma unroll
            for (int cmp = 0; cmp < 2; cmp++) {
                float s = fmaf(-0.5f, mahaS[cmp * 64 + tid], g_constk[kk + cmp]);
                if (s > runm) {
                    runs = runs * expf(runm - s) + 1.0f;
                    runm = s;
                } else {
                    runs += expf(s - runm);
                }
            }
        }
    }

    __syncthreads();
    if (tid < 64) dred[tid] = (double)(runm + logf(runs));
    __syncthreads();
    for (int s2 = 32; s2 > 0; s2 >>= 1) {
        if (tid < s2) dred[tid] += dred[tid + s2];
        __syncthreads();
    }
    if (tid == 0) g_partial[blockIdx.x] = dred[0];
}

// ============================================================
// Kernel 3: deterministic final reduction. 1 block x 512 threads.
// ============================================================
__global__ void final_kernel(float* __restrict__ out) {
    __shared__ double dd[512];
    int t = threadIdx.x;
    dd[t] = g_partial[t];
    __syncthreads();
    for (int s = 256; s > 0; s >>= 1) {
        if (t < s) dd[t] += dd[t + s];
        __syncthreads();
    }
    if (t == 0) out[0] = (float)(-dd[0] / (double)BTOT);
}

// ============================================================
extern "C" void kernel_launch(void* const* d_in, const int* in_sizes, int n_in,
                              void* d_out, int out_size) {
    const float* x           = (const float*)d_in[0];
    const float* means_raw   = (const float*)d_in[1];
    const float* scale_raw   = (const float*)d_in[2];
    const float* weights_raw = (const float*)d_in[3];
    float* out = (float*)d_out;

    cudaFuncSetAttribute(main_kernel, cudaFuncAttributeMaxDynamicSharedMemorySize,
                         SMEM_BYTES);

    logw_kernel<<<1, 64>>>(weights_raw);
    prep_kernel<<<64, 64>>>(means_raw, scale_raw);
    main_kernel<<<512, 256, SMEM_BYTES>>>(x);
    final_kernel<<<1, 512>>>(out);
}

// round 3
// speedup vs baseline: 4.3103x; 4.3103x over previous
#include <cuda_runtime.h>
#include <cuda_bf16.h>
#include <cstdint>
#include <math.h>

#define BTOT 32768
#define KC 64
#define DD 64
#define LOG_2PI 1.8378770664093453f

// ---- persistent scratch ----
__device__ __nv_bfloat16 g_LinvBF[KC][DD * DD];  // [k][i*64+j] = Linv_k[i][j]
__device__ __nv_bfloat16 g_Db[KC * DD];          // [kc][j] = d_kc[j] = (Linv^T c)[j]
__device__ float  g_const2[KC];   // logw - hld - 0.5*D*log2pi - 0.5*||c||^2
__device__ float  g_logw[KC];
__device__ double g_partial[256];

// ============================================================
// Kernel 0: log-softmax of weights
// ============================================================
__global__ void logw_kernel(const float* __restrict__ w) {
    __shared__ float red[KC];
    int t = threadIdx.x;
    float v = w[t] * 0.125f;
    red[t] = v;
    __syncthreads();
    for (int s = 32; s > 0; s >>= 1) {
        if (t < s) red[t] = fmaxf(red[t], red[t + s]);
        __syncthreads();
    }
    float m = red[0];
    __syncthreads();
    red[t] = expf(v - m);
    __syncthreads();
    for (int s = 32; s > 0; s >>= 1) {
        if (t < s) red[t] += red[t + s];
        __syncthreads();
    }
    g_logw[t] = v - (m + logf(red[0]));
}

// ============================================================
// Kernel 1: per-component preprocess (64 blocks x 64 threads)
// ============================================================
__global__ void prep_kernel(const float* __restrict__ means_raw,
                            const float* __restrict__ scale_raw) {
    const int k = blockIdx.x;
    const int t = threadIdx.x;
    __shared__ float L[DD][DD + 1];
    __shared__ float Y[DD][DD + 1];   // Y[j][i] = Linv[i][j] (column j)
    __shared__ float red[DD];
    __shared__ float mv[DD];
    __shared__ float cS[DD];
    const float g2 = 1.0f / 512.0f;
    const float g1 = 1.0f / 64.0f;

    for (int i = 0; i < DD; i++)
        L[i][t] = scale_raw[(k * DD + i) * DD + t] * g2;
    mv[t] = means_raw[k * DD + t] * g1;
    __syncthreads();

    red[t] = L[t][t];   // half_log_det = sum of pre-diagonal
    __syncthreads();
    for (int s = 32; s > 0; s >>= 1) {
        if (t < s) red[t] += red[t + s];
        __syncthreads();
    }
    float hld = red[0];
    __syncthreads();

    {   // row t of L: strict lower kept, exp on diag, zero above
        float dg = expf(L[t][t]);
        for (int j = t; j < DD; j++) L[t][j] = (j == t) ? dg : 0.0f;
    }
    __syncthreads();

    // forward substitution: column t of Linv
    for (int i = 0; i < t; i++) Y[t][i] = 0.0f;
    Y[t][t] = 1.0f / L[t][t];
    for (int i = t + 1; i < DD; i++) {
        float s = 0.0f;
        for (int m = t; m < i; m++) s += L[i][m] * Y[t][m];
        Y[t][i] = -s / L[i][i];
    }
    __syncthreads();

    // c[t] = sum_j Linv[t][j] mu[j] = sum_{j<=t} Y[j][t] mu[j]
    float c = 0.0f;
    for (int j = 0; j <= t; j++) c += Y[j][t] * mv[j];
    cS[t] = c;
    __syncthreads();

    // d[t] = sum_i Linv[i][t] c[i] = sum_i Y[t][i] cS[i]
    float d = 0.0f;
    for (int i = t; i < DD; i++) d += Y[t][i] * cS[i];
    g_Db[k * DD + t] = __float2bfloat16(d);

    // e = ||c||^2
    red[t] = c * c;
    __syncthreads();
    for (int s = 32; s > 0; s >>= 1) {
        if (t < s) red[t] += red[t + s];
        __syncthreads();
    }
    float e = red[0];

    // Linv bf16, row-major [i][j]; thread t owns column t
    for (int i = 0; i < DD; i++)
        g_LinvBF[k][i * DD + t] = __float2bfloat16(Y[t][i]);

    if (t == 0)
        g_const2[k] = g_logw[k] - hld - 0.5f * 64.0f * LOG_2PI - 0.5f * e;
}

// ============================================================
// Main kernel: bf16 HMMA. 256 CTAs x 128 thr. CTA tile: 128 rows.
// Warp tile: M=32, N=64. smem rows padded to 72 bf16 (144B) ->
// conflict-free ldmatrix.
// ============================================================
#define ROWB 144                    // bytes per smem row (72 bf16)
#define XS_BYTES (128 * ROWB)       // 18432
#define LB_BYTES (64 * ROWB)        // 9216 per buffer
#define GS_OFF   (XS_BYTES + 2 * LB_BYTES)        // 36864
#define GS_BYTES (128 * 65 * 4)                   // 33280
#define DSM_OFF  (GS_OFF + GS_BYTES)              // 70144
#define SMEM_TOTAL (DSM_OFF + 4 * 8)              // 70176

__device__ __forceinline__ void ldmx4(uint32_t a[4], uint32_t addr) {
    asm volatile("ldmatrix.sync.aligned.m8n8.x4.shared.b16 {%0,%1,%2,%3}, [%4];"
                 : "=r"(a[0]), "=r"(a[1]), "=r"(a[2]), "=r"(a[3]) : "r"(addr));
}
__device__ __forceinline__ void mma16816(float d[4], const uint32_t a[4],
                                         uint32_t b0, uint32_t b1) {
    asm volatile(
        "mma.sync.aligned.m16n8k16.row.col.f32.bf16.bf16.f32 "
        "{%0,%1,%2,%3}, {%4,%5,%6,%7}, {%8,%9}, {%0,%1,%2,%3};"
        : "+f"(d[0]), "+f"(d[1]), "+f"(d[2]), "+f"(d[3])
        : "r"(a[0]), "r"(a[1]), "r"(a[2]), "r"(a[3]), "r"(b0), "r"(b1));
}
__device__ __forceinline__ void cp_lb(uint32_t dstBase,
                                      const __nv_bfloat16* src, int t) {
#pragma unroll
    for (int q = 0; q < 4; q++) {
        int f = t + q * 128;            // 0..511 16B chunks
        uint32_t dst = dstBase + (f >> 3) * ROWB + (f & 7) * 16;
        asm volatile("cp.async.ca.shared.global [%0], [%1], 16;"
                     :: "r"(dst), "l"(src + f * 8));
    }
}

// compute acc[2][8][4] = (32x64) = Xwarp(32x64) * B(64x64)^T
__device__ __forceinline__ void gemm_tile(float acc[2][8][4],
                                          uint32_t XsW, uint32_t LbB, int l) {
#pragma unroll
    for (int ma = 0; ma < 2; ma++)
#pragma unroll
        for (int n8 = 0; n8 < 8; n8++)
#pragma unroll
            for (int q = 0; q < 4; q++) acc[ma][n8][q] = 0.0f;

    const int lr = (l & 15);
    const int lc = (l >> 4) * 16;       // byte offset for hi chunk
#pragma unroll
    for (int ks = 0; ks < 4; ks++) {
        uint32_t a[2][4];
#pragma unroll
        for (int ma = 0; ma < 2; ma++)
            ldmx4(a[ma], XsW + (ma * 16 + lr) * ROWB + ks * 32 + lc);
        uint32_t b[8][2];
#pragma unroll
        for (int ng = 0; ng < 4; ng++) {
            uint32_t r[4];
            ldmx4(r, LbB + (ng * 16 + lr) * ROWB + ks * 32 + lc);
            b[2 * ng][0] = r[0]; b[2 * ng][1] = r[2];
            b[2 * ng + 1][0] = r[1]; b[2 * ng + 1][1] = r[3];
        }
#pragma unroll
        for (int ma = 0; ma < 2; ma++)
#pragma unroll
            for (int n8 = 0; n8 < 8; n8++)
                mma16816(acc[ma][n8], a[ma], b[n8][0], b[n8][1]);
    }
}

__global__ __launch_bounds__(128) void main_kernel(const float* __restrict__ x) {
    extern __shared__ char smem[];
    __nv_bfloat16* Xs = (__nv_bfloat16*)smem;
    float* gS = (float*)(smem + GS_OFF);
    double* dsm = (double*)(smem + DSM_OFF);

    const int t = threadIdx.x;
    const int w = t >> 5, l = t & 31;
    const int m0w = w * 32;
    const int b0 = blockIdx.x * 128;
    uint32_t sbase = (uint32_t)__cvta_generic_to_shared(smem);
    uint32_t XsA = sbase;
    uint32_t LbA = sbase + XS_BYTES;
    uint32_t XsW = XsA + m0w * ROWB;

    // ---- load X tile (128x64 f32) -> bf16 smem, pad-72 rows ----
    {
        const float4* X4 = (const float4*)(x + (size_t)b0 * 64);
#pragma unroll
        for (int q = 0; q < 16; q++) {
            int f = t + q * 128;            // 0..2047
            int row = f >> 4, cq = f & 15;
            float4 v = X4[f];
            __nv_bfloat162 p0 = __float22bfloat162_rn(make_float2(v.x, v.y));
            __nv_bfloat162 p1 = __float22bfloat162_rn(make_float2(v.z, v.w));
            uint2 pk;
            pk.x = *reinterpret_cast<uint32_t*>(&p0);
            pk.y = *reinterpret_cast<uint32_t*>(&p1);
            *reinterpret_cast<uint2*>(&Xs[row * 72 + cq * 4]) = pk;
        }
    }

    float acc[2][8][4];

    // ---- G phase: G = X * D^T for all components ----
    cp_lb(LbA, g_Db, t);
    asm volatile("cp.async.commit_group;");
    asm volatile("cp.async.wait_group 0;");
    __syncthreads();
    gemm_tile(acc, XsW, LbA, l);
#pragma unroll
    for (int ma = 0; ma < 2; ma++)
#pragma unroll
        for (int n8 = 0; n8 < 8; n8++) {
            int row = m0w + ma * 16 + (l >> 2);
            int col = n8 * 8 + (l & 3) * 2;
            gS[row * 65 + col] = acc[ma][n8][0];
            gS[row * 65 + col + 1] = acc[ma][n8][1];
            gS[(row + 8) * 65 + col] = acc[ma][n8][2];
            gS[(row + 8) * 65 + col + 1] = acc[ma][n8][3];
        }
    __syncthreads();   // gS visible; Lb free for reload

    // ---- prologue: stage Linv[0], Linv[1] ----
    cp_lb(LbA, g_LinvBF[0], t);
    asm volatile("cp.async.commit_group;");
    cp_lb(LbA + LB_BYTES, g_LinvBF[1], t);
    asm volatile("cp.async.commit_group;");

    float runm[4], runs[4];
#pragma unroll
    for (int i = 0; i < 4; i++) { runm[i] = -INFINITY; runs[i] = 0.0f; }

    for (int k = 0; k < KC; k++) {
        const int buf = k & 1;
        asm volatile("cp.async.wait_group 1;");
        __syncthreads();

        gemm_tile(acc, XsW, LbA + buf * LB_BYTES, l);

        // sum of squares per row (2 row-partials per ma-group)
        float p[4];
#pragma unroll
        for (int ma = 0; ma < 2; ma++) {
            float s0 = 0.0f, s1 = 0.0f;
#pragma unroll
            for (int n8 = 0; n8 < 8; n8++) {
                s0 = fmaf(acc[ma][n8][0], acc[ma][n8][0], s0);
                s0 = fmaf(acc[ma][n8][1], acc[ma][n8][1], s0);
                s1 = fmaf(acc[ma][n8][2], acc[ma][n8][2], s1);
                s1 = fmaf(acc[ma][n8][3], acc[ma][n8][3], s1);
            }
            p[ma * 2] = s0; p[ma * 2 + 1] = s1;
        }
#pragma unroll
        for (int off = 1; off <= 2; off <<= 1)
#pragma unroll
            for (int i = 0; i < 4; i++)
                p[i] += __shfl_xor_sync(0xffffffffu, p[i], off);

        if ((l & 3) == 0) {
            float c2 = g_const2[k];
#pragma unroll
            for (int i = 0; i < 4; i++) {
                int row = m0w + (i >> 1) * 16 + (i & 1) * 8 + (l >> 2);
                float g = gS[row * 65 + k];
                float s = c2 - 0.5f * p[i] + g;
                float nm = fmaxf(runm[i], s);
                runs[i] = runs[i] * __expf(runm[i] - nm) + __expf(s - nm);
                runm[i] = nm;
            }
        }

        __syncthreads();   // all warps done reading buf
        if (k + 2 < KC) cp_lb(LbA + buf * LB_BYTES, g_LinvBF[k + 2], t);
        asm volatile("cp.async.commit_group;");
    }

    // ---- per-CTA deterministic reduction ----
    double lps = 0.0;
    if ((l & 3) == 0) {
#pragma unroll
        for (int i = 0; i < 4; i++)
            lps += (double)(runm[i] + logf(runs[i]));
    }
#pragma unroll
    for (int off = 16; off > 0; off >>= 1)
        lps += __shfl_xor_sync(0xffffffffu, lps, off);
    if (l == 0) dsm[w] = lps;
    __syncthreads();
    if (t == 0)
        g_partial[blockIdx.x] = dsm[0] + dsm[1] + dsm[2] + dsm[3];
}

// ============================================================
// Final deterministic reduction (256 partials)
// ============================================================
__global__ void final_kernel(float* __restrict__ out) {
    __shared__ double dd[256];
    int t = threadIdx.x;
    dd[t] = g_partial[t];
    __syncthreads();
    for (int s = 128; s > 0; s >>= 1) {
        if (t < s) dd[t] += dd[t + s];
        __syncthreads();
    }
    if (t == 0) out[0] = (float)(-dd[0] / (double)BTOT);
}

// ============================================================
extern "C" void kernel_launch(void* const* d_in, const int* in_sizes, int n_in,
                              void* d_out, int out_size) {
    const float* x           = (const float*)d_in[0];
    const float* means_raw   = (const float*)d_in[1];
    const float* scale_raw   = (const float*)d_in[2];
    const float* weights_raw = (const float*)d_in[3];
    float* out = (float*)d_out;

    cudaFuncSetAttribute(main_kernel, cudaFuncAttributeMaxDynamicSharedMemorySize,
                         SMEM_TOTAL);

    logw_kernel<<<1, 64>>>(weights_raw);
    prep_kernel<<<64, 64>>>(means_raw, scale_raw);
    main_kernel<<<256, 128, SMEM_TOTAL>>>(x);
    final_kernel<<<1, 256>>>(out);
}